// round 9
// baseline (speedup 1.0000x reference)
#include <cuda_runtime.h>
#include <cuda_bf16.h>
#include <cuda_fp8.h>
#include <cstdint>

#define B_ 128
#define T_ 500
#define D_ 700
#define H_ 512
#define O_ 20
#define K1 768       // GEMM1 K: D padded to 768 fp8 (6 stages of 128)
#define K2 512       // GEMM2 K: H (4 stages of 128)
#define SBUF 16384   // one stage buffer: 128 rows x 128 B (SW128 swizzled)
#define STG 3        // cp.async pipeline depth
#define GSMEM (2 * STG * SBUF)   // 98304 bytes dynamic smem
#define ERS 272      // epilogue smem row stride (256 data + 16 -> conflict-free stores)

// ---------------- scratch (static device globals: no allocation allowed) ----------------
__device__ uint8_t       g_xc[(size_t)T_ * B_ * K1];   // 49 MB  x as e4m3 [t][b][k]
__device__ uint8_t       g_w1[(size_t)H_ * K1];        // W1 e4m3 [h][k]
__device__ uint8_t       g_w2[(size_t)H_ * K2];        // W2 e4m3 [g][h]
__device__ __nv_bfloat16 g_cur[(size_t)T_ * B_ * H_];  // 65 MB  cur1 then cur2 [t][b][h]
__device__ uint8_t       g_s1[(size_t)T_ * B_ * H_];   // 33 MB  s1 e4m3 (0 or 1) [t][b][h]
__device__ float         g_S2[B_ * H_];                // sum over t of s2

// ---------------- helpers ----------------
__device__ __forceinline__ uint32_t smem_u32(const void* p) {
    uint32_t a;
    asm("{ .reg .u64 t; cvta.to.shared.u64 t, %1; cvt.u32.u64 %0, t; }" : "=r"(a) : "l"(p));
    return a;
}
__device__ __forceinline__ void cp16(uint32_t s, const void* g) {
    asm volatile("cp.async.cg.shared.global [%0], [%1], 16;" :: "r"(s), "l"(g));
}
__device__ __forceinline__ void ldsm4(uint32_t& r0, uint32_t& r1, uint32_t& r2,
                                      uint32_t& r3, uint32_t addr) {
    asm volatile("ldmatrix.sync.aligned.m8n8.x4.shared.b16 {%0,%1,%2,%3}, [%4];"
                 : "=r"(r0), "=r"(r1), "=r"(r2), "=r"(r3) : "r"(addr));
}
__device__ __forceinline__ void mma16832f8(float* c, const uint32_t* a, const uint32_t* b) {
    asm volatile(
        "mma.sync.aligned.m16n8k32.row.col.f32.e4m3.e4m3.f32 "
        "{%0,%1,%2,%3}, {%4,%5,%6,%7}, {%8,%9}, {%0,%1,%2,%3};"
        : "+f"(c[0]), "+f"(c[1]), "+f"(c[2]), "+f"(c[3])
        : "r"(a[0]), "r"(a[1]), "r"(a[2]), "r"(a[3]), "r"(b[0]), "r"(b[1]));
}
__device__ __forceinline__ uint32_t sw128(uint32_t off) {   // SW128: bits[9:7] ^-> [6:4]
    return off ^ ((off >> 3) & 0x70u);
}
__device__ __forceinline__ uint32_t f4_to_e4m3x4(float4 v) {
    uint32_t lo = __nv_cvt_float2_to_fp8x2(make_float2(v.x, v.y),
                                           __NV_SATFINITE, __NV_E4M3);
    uint32_t hi = __nv_cvt_float2_to_fp8x2(make_float2(v.z, v.w),
                                           __NV_SATFINITE, __NV_E4M3);
    return (lo & 0xffffu) | (hi << 16);
}

// ---------------- prep: fp32 -> e4m3 (grid-stride over 4B output chunks) --------------
__global__ __launch_bounds__(256) void prep_x(const float* __restrict__ x) {
    const int total = B_ * T_ * (K1 / 4);              // 192 u32-chunks per row (incl pad)
    for (int c = blockIdx.x * 256 + threadIdx.x; c < total; c += gridDim.x * 256) {
        const int bt = c / (K1 / 4), i = c - bt * (K1 / 4);   // x is [B][T][D]
        const int b = bt / T_, t = bt - b * T_;
        uint32_t* o = (uint32_t*)(g_xc + ((size_t)t * B_ + b) * K1);
        if (i < 175) {   // 175 chunks cover d = 0..699 exactly
            float4 v = ((const float4*)(x + (size_t)bt * D_))[i];
            o[i] = f4_to_e4m3x4(v);
        } else {
            o[i] = 0u;   // pad 700..767
        }
    }
}
__global__ void prep_w1(const float* __restrict__ W1) {
    const int h = blockIdx.x;
    const float* wr = W1 + (size_t)h * D_;
    uint8_t* o = g_w1 + (size_t)h * K1;
    for (int d = threadIdx.x; d < D_; d += 256)
        o[d] = __nv_cvt_float_to_fp8(wr[d], __NV_SATFINITE, __NV_E4M3);
    for (int d = D_ + threadIdx.x; d < K1; d += 256) o[d] = 0;
}
__global__ void prep_w2(const float* __restrict__ W2) {
    int i = blockIdx.x * blockDim.x + threadIdx.x;
    if (i < H_ * H_)
        g_w2[i] = __nv_cvt_float_to_fp8(W2[i], __NV_SATFINITE, __NV_E4M3);
}

// ---------------- GEMM (fp8): out[t*B+m][n] = bf16(A[t*B+m][:].Bm[n][:] + bias[n]) ----
// grid (4 n-tiles, 500 t), 256 threads. CTA tile M=128 x N=128, K=KB e4m3 (KB%128==0).
// 8 warps as 2(m)x4(n), each 64x32 via m16n8k32. K-stage 128B (SW128), 3-stage ring.
template <int KB>
__global__ __launch_bounds__(256, 2) void gemm_f8(const uint8_t* __restrict__ Asrc,
                                                  const uint8_t* __restrict__ Bsrc,
                                                  const float* __restrict__ bias,
                                                  __nv_bfloat16* __restrict__ outp) {
    constexpr int NS = KB / 128;
    extern __shared__ __align__(128) char smem[];
    const int tid = threadIdx.x, lane = tid & 31, wid = tid >> 5;
    const int t = blockIdx.y, nbase = blockIdx.x * 128;
    const int wm = wid >> 2, wn = wid & 3;    // warp tile: rows wm*64, cols wn*32

    const char* gA = (const char*)Asrc + (size_t)t * B_ * KB;
    const char* gB = (const char*)Bsrc + (size_t)nbase * KB;
    const uint32_t sAu = smem_u32(smem);
    const uint32_t sBu = sAu + STG * SBUF;

    // loader: thread -> row tid>>1, 64B half-row (tid&1), 4 x 16B chunks
    const int lrow = tid >> 1;
    const int lhalf = (tid & 1) * 64;
    const size_t grow = (size_t)lrow * KB;

    const int arow = lane & 15;
    const int acol = (lane >> 4) * 16;
    const int brow = (lane & 7) + ((lane & 16) ? 8 : 0);
    const int bcol = (lane & 8) ? 16 : 0;

    float acc[4][4][4];
#pragma unroll
    for (int i = 0; i < 4; i++)
#pragma unroll
        for (int j = 0; j < 4; j++)
#pragma unroll
            for (int q = 0; q < 4; q++) acc[i][j][q] = 0.f;

#define LOADSTAGE(s, buf)                                                       \
    do {                                                                        \
        const char* ga = gA + grow + (s) * 128 + lhalf;                         \
        const char* gb = gB + grow + (s) * 128 + lhalf;                         \
        const uint32_t rb = (uint32_t)(lrow * 128 + lhalf);                     \
        _Pragma("unroll")                                                       \
        for (int j = 0; j < 4; j++) {                                           \
            uint32_t sw = sw128(rb + j * 16);                                   \
            cp16(sAu + (buf) * SBUF + sw, ga + j * 16);                         \
            cp16(sBu + (buf) * SBUF + sw, gb + j * 16);                         \
        }                                                                       \
    } while (0)

    // prologue: fill STG-1 = 2 stages
#pragma unroll
    for (int p = 0; p < STG - 1; p++) {
        LOADSTAGE(p, p);
        asm volatile("cp.async.commit_group;");
    }

    int buf = 0, nbuf = STG - 1;
    for (int s = 0; s < NS; s++) {
        asm volatile("cp.async.wait_group 1;");   // stage s resident
        __syncthreads();
        if (s + STG - 1 < NS) LOADSTAGE(s + STG - 1, nbuf);
        asm volatile("cp.async.commit_group;");

        const uint32_t abase = sAu + buf * SBUF;
        const uint32_t bbase = sBu + buf * SBUF;
#pragma unroll
        for (int ks = 0; ks < 4; ks++) {          // 32 fp8 (= 32 bytes) per k-step
            uint32_t a[4][4], bf[4][2];
#pragma unroll
            for (int i = 0; i < 4; i++)
                ldsm4(a[i][0], a[i][1], a[i][2], a[i][3],
                      abase + sw128((wm * 64 + i * 16 + arow) * 128 + ks * 32 + acol));
#pragma unroll
            for (int j = 0; j < 2; j++)
                ldsm4(bf[2 * j][0], bf[2 * j][1], bf[2 * j + 1][0], bf[2 * j + 1][1],
                      bbase + sw128((wn * 32 + j * 16 + brow) * 128 + ks * 32 + bcol));
#pragma unroll
            for (int i = 0; i < 4; i++)
#pragma unroll
                for (int j = 0; j < 4; j++) mma16832f8(acc[i][j], a[i], bf[j]);
        }
        buf = (buf + 1 == STG) ? 0 : buf + 1;
        nbuf = (nbuf + 1 == STG) ? 0 : nbuf + 1;
    }
    __syncthreads();   // all compute done; smem reusable for epilogue staging

    // epilogue: acc -> smem bf16 (row stride ERS, conflict-free), then coalesced copy.
    const int r0 = wm * 64 + (lane >> 2);
    const int cb = wn * 32 + (lane & 3) * 2;
#pragma unroll
    for (int j = 0; j < 4; j++) {
        const int col = nbase + cb + j * 8;
        const float2 bl = *(const float2*)(bias + col);
#pragma unroll
        for (int i = 0; i < 4; i++) {
            const int rb = r0 + i * 16;
            __nv_bfloat162 v0 = __floats2bfloat162_rn(acc[i][j][0] + bl.x,
                                                      acc[i][j][1] + bl.y);
            __nv_bfloat162 v1 = __floats2bfloat162_rn(acc[i][j][2] + bl.x,
                                                      acc[i][j][3] + bl.y);
            *(uint32_t*)(smem + rb * ERS + (cb + j * 8) * 2)       = *(uint32_t*)&v0;
            *(uint32_t*)(smem + (rb + 8) * ERS + (cb + j * 8) * 2) = *(uint32_t*)&v1;
        }
    }
    __syncthreads();
    // 128 rows x 256B -> global; 16B chunks, fully coalesced 256B segments
    char* gOut = (char*)outp + ((size_t)t * B_ * H_ + nbase) * 2;
#pragma unroll
    for (int c = tid; c < 2048; c += 256) {
        const int row = c >> 4, off = (c & 15) * 16;
        uint4 v = *(const uint4*)(smem + row * ERS + off);
        *(uint4*)(gOut + (size_t)row * (H_ * 2) + off) = v;
    }
}

// ---------------- scan1: LIF over cur1 (bf16x2), writes s1 as e4m3 pairs ---------------
// grid (2 h-halves, 128 b), 128 threads; thread = one (b, h-pair). No barriers.
__global__ __launch_bounds__(128) void scan1_kernel() {
    const int q = blockIdx.x, b = blockIdx.y;
    const int tid = threadIdx.x;
    const size_t off2 = (size_t)b * (H_ / 2) + q * 128 + tid;   // pair index
    const __nv_bfloat162* cp = (const __nv_bfloat162*)g_cur + off2;
    uint16_t* sp = (uint16_t*)g_s1 + off2;
    const int stride = B_ * H_ / 2;
    float v0 = 0.f, v1 = 0.f;
    for (int t0 = 0; t0 < T_; t0 += 10) {
        __nv_bfloat162 I[10];
#pragma unroll
        for (int u = 0; u < 10; u++)
            I[u] = cp[(size_t)(t0 + u) * stride];
#pragma unroll
        for (int u = 0; u < 10; u++) {
            float2 f = __bfloat1622float2(I[u]);
            v0 += (f.x - v0) * 0.5f;
            v1 += (f.y - v1) * 0.5f;
            bool s0 = (v0 >= 1.0f), s1v = (v1 >= 1.0f);
            // e4m3 1.0 = 0x38
            sp[(size_t)(t0 + u) * stride] =
                (uint16_t)((s0 ? 0x38u : 0u) | ((s1v ? 0x38u : 0u) << 8));
            if (s0) v0 = 0.f;
            if (s1v) v1 = 0.f;
        }
    }
}

// ---------------- scan2: LIF over cur2 (bf16x2), accumulates spike counts -> S2 --------
__global__ __launch_bounds__(128) void scan2_kernel() {
    const int q = blockIdx.x, b = blockIdx.y;
    const int tid = threadIdx.x;
    const size_t off2 = (size_t)b * (H_ / 2) + q * 128 + tid;
    const __nv_bfloat162* cp = (const __nv_bfloat162*)g_cur + off2;
    const int stride = B_ * H_ / 2;
    float v0 = 0.f, v1 = 0.f, c0 = 0.f, c1 = 0.f;
    for (int t0 = 0; t0 < T_; t0 += 10) {
        __nv_bfloat162 I[10];
#pragma unroll
        for (int u = 0; u < 10; u++)
            I[u] = cp[(size_t)(t0 + u) * stride];
#pragma unroll
        for (int u = 0; u < 10; u++) {
            float2 f = __bfloat1622float2(I[u]);
            v0 += (f.x - v0) * 0.5f;
            v1 += (f.y - v1) * 0.5f;
            if (v0 >= 1.0f) { v0 = 0.f; c0 += 1.f; }
            if (v1 >= 1.0f) { v1 = 0.f; c1 += 1.f; }
        }
    }
    float2* o = (float2*)(g_S2 + 2 * off2);
    *o = make_float2(c0, c1);
}

// ---------------- final: out[b,o] = 500*b3[o] + sum_h S2[b,h] * W3[o,h] ----------------
__global__ void final_kernel(const float* __restrict__ W3, const float* __restrict__ b3,
                             float* __restrict__ out) {
    __shared__ float sW3[O_ * H_];
    __shared__ float part[4 * O_];
    const int b = blockIdx.x, tid = threadIdx.x;
    for (int i = tid; i < O_ * H_; i += 128) sW3[i] = W3[i];
    __syncthreads();

    float acc[O_];
#pragma unroll
    for (int o = 0; o < O_; o++) acc[o] = 0.f;
    for (int h = tid; h < H_; h += 128) {
        float s2 = g_S2[b * H_ + h];
#pragma unroll
        for (int o = 0; o < O_; o++) acc[o] += s2 * sW3[o * H_ + h];
    }
#pragma unroll
    for (int off = 16; off; off >>= 1)
#pragma unroll
        for (int o = 0; o < O_; o++)
            acc[o] += __shfl_down_sync(0xffffffffu, acc[o], off);
    if ((tid & 31) == 0)
#pragma unroll
        for (int o = 0; o < O_; o++) part[(tid >> 5) * O_ + o] = acc[o];
    __syncthreads();
    if (tid < O_) {
        float r = 500.0f * b3[tid];
#pragma unroll
        for (int w = 0; w < 4; w++) r += part[w * O_ + tid];
        out[b * O_ + tid] = r;
    }
}

// ---------------- launch ----------------
extern "C" void kernel_launch(void* const* d_in, const int* in_sizes, int n_in,
                              void* d_out, int out_size) {
    const float* x  = (const float*)d_in[0];   // [128, 500, 700]
    const float* W1 = (const float*)d_in[1];   // [512, 700]
    const float* b1 = (const float*)d_in[2];   // [512]
    const float* W2 = (const float*)d_in[3];   // [512, 512]
    const float* b2 = (const float*)d_in[4];   // [512]
    const float* W3 = (const float*)d_in[5];   // [20, 512]
    const float* b3 = (const float*)d_in[6];   // [20]
    float* out = (float*)d_out;                // [128, 20]

    uint8_t* xc;  cudaGetSymbolAddress((void**)&xc,  g_xc);
    uint8_t* w1c; cudaGetSymbolAddress((void**)&w1c, g_w1);
    uint8_t* w2c; cudaGetSymbolAddress((void**)&w2c, g_w2);
    uint8_t* s1c; cudaGetSymbolAddress((void**)&s1c, g_s1);
    __nv_bfloat16* curc; cudaGetSymbolAddress((void**)&curc, g_cur);

    cudaFuncSetAttribute(gemm_f8<K1>, cudaFuncAttributeMaxDynamicSharedMemorySize, GSMEM);
    cudaFuncSetAttribute(gemm_f8<K2>, cudaFuncAttributeMaxDynamicSharedMemorySize, GSMEM);

    prep_x<<<8192, 256>>>(x);
    prep_w1<<<H_, 256>>>(W1);
    prep_w2<<<(H_ * H_ + 255) / 256, 256>>>(W2);
    gemm_f8<K1><<<dim3(H_ / 128, T_), 256, GSMEM>>>(xc, w1c, b1, curc);   // cur1
    scan1_kernel<<<dim3(2, B_), 128>>>();                                 // s1 (e4m3)
    gemm_f8<K2><<<dim3(H_ / 128, T_), 256, GSMEM>>>(s1c, w2c, b2, curc);  // cur2
    scan2_kernel<<<dim3(2, B_), 128>>>();                                 // S2 counts
    final_kernel<<<B_, 128>>>(W3, b3, out);
}